// round 1
// baseline (speedup 1.0000x reference)
#include <cuda_runtime.h>
#include <math.h>

#define BB 2
#define LL 32
#define NSLOPE 0.01f

// ---------------- scratch (static __device__, no allocs) ----------------
__device__ float g_h1p0[2*4*128*128];
__device__ float g_h1p1[2*8*64*64];
__device__ float g_h1p2[2*16*32*32];
__device__ float g_h1p3[2*16*16*16];

__device__ float g_f0[2*4*256*256];    // feats[0] (pre-pool h2)
__device__ float g_f1[2*8*128*128];
__device__ float g_f2[2*16*64*64];
__device__ float g_f3[2*16*32*32];

__device__ float g_h2p0[2*4*128*128];  // pooled h2
__device__ float g_h2p1[2*8*64*64];
__device__ float g_h2p2[2*16*32*32];
__device__ float g_h2p3[2*16*16*16];

__device__ float g_attn0[64*128*128];  // stored (b*L+l, y, x)
__device__ float g_attn1[64*64*64];
__device__ float g_attn2[64*32*32];
__device__ float g_attn3[64*16*16];

__device__ float g_d0[64*16*32*32];
__device__ float g_d1[64*8*64*64];
__device__ float g_d2[64*4*128*128];

static inline int cdiv(int a, int b) { return (a + b - 1) / b; }

__device__ __forceinline__ float leaky(float v) { return v >= 0.f ? v : NSLOPE * v; }

// ---------------- encoder: 5x5 conv (pad 2) + leaky ----------------
__global__ void conv5_leaky_k(const float* __restrict__ in, const float* __restrict__ w,
                              const float* __restrict__ bias, float* __restrict__ out,
                              int N, int Ci, int Co, int H, int W) {
    int tid = blockIdx.x * blockDim.x + threadIdx.x;
    int total = N * Co * H * W;
    if (tid >= total) return;
    int x = tid % W;
    int y = (tid / W) % H;
    int co = (tid / (W * H)) % Co;
    int n = tid / (W * H * Co);

    float acc = bias[co];
    bool interior = (y >= 2 && y < H - 2 && x >= 2 && x < W - 2);
    for (int ci = 0; ci < Ci; ci++) {
        const float* ip = in + (n * Ci + ci) * H * W;
        const float* wp = w + (co * Ci + ci) * 25;
        if (interior) {
#pragma unroll
            for (int ky = 0; ky < 5; ky++) {
                const float* row = ip + (y + ky - 2) * W + x - 2;
#pragma unroll
                for (int kx = 0; kx < 5; kx++)
                    acc += row[kx] * wp[ky * 5 + kx];
            }
        } else {
#pragma unroll
            for (int ky = 0; ky < 5; ky++) {
                int yy = y + ky - 2;
                if (yy < 0 || yy >= H) continue;
#pragma unroll
                for (int kx = 0; kx < 5; kx++) {
                    int xx = x + kx - 2;
                    if (xx < 0 || xx >= W) continue;
                    acc += ip[yy * W + xx] * wp[ky * 5 + kx];
                }
            }
        }
    }
    out[tid] = leaky(acc);
}

// ---------------- fused conv5 + leaky + maxpool2 (h1 path) ----------------
__global__ void conv5_leaky_pool_k(const float* __restrict__ in, const float* __restrict__ w,
                                   const float* __restrict__ bias, float* __restrict__ out,
                                   int N, int Ci, int Co, int H, int W) {
    int Hp = H >> 1, Wp = W >> 1;
    int tid = blockIdx.x * blockDim.x + threadIdx.x;
    int total = N * Co * Hp * Wp;
    if (tid >= total) return;
    int px = tid % Wp;
    int py = (tid / Wp) % Hp;
    int co = (tid / (Wp * Hp)) % Co;
    int n = tid / (Wp * Hp * Co);

    float m = -INFINITY;
#pragma unroll
    for (int dy = 0; dy < 2; dy++) {
#pragma unroll
        for (int dx = 0; dx < 2; dx++) {
            int y = 2 * py + dy, x = 2 * px + dx;
            float acc = bias[co];
            for (int ci = 0; ci < Ci; ci++) {
                const float* ip = in + (n * Ci + ci) * H * W;
                const float* wp = w + (co * Ci + ci) * 25;
#pragma unroll
                for (int ky = 0; ky < 5; ky++) {
                    int yy = y + ky - 2;
                    if (yy < 0 || yy >= H) continue;
#pragma unroll
                    for (int kx = 0; kx < 5; kx++) {
                        int xx = x + kx - 2;
                        if (xx < 0 || xx >= W) continue;
                        acc += ip[yy * W + xx] * wp[ky * 5 + kx];
                    }
                }
            }
            m = fmaxf(m, acc);
        }
    }
    out[tid] = leaky(m);  // leaky monotone: leaky(max) == max(leaky)
}

// ---------------- maxpool 2x2 (h2 path) ----------------
__global__ void maxpool_k(const float* __restrict__ in, float* __restrict__ out,
                          int NC, int H, int W) {
    int Hp = H >> 1, Wp = W >> 1;
    int tid = blockIdx.x * blockDim.x + threadIdx.x;
    int total = NC * Hp * Wp;
    if (tid >= total) return;
    int px = tid % Wp;
    int py = (tid / Wp) % Hp;
    int nc = tid / (Wp * Hp);
    const float* ip = in + nc * H * W;
    int y = 2 * py, x = 2 * px;
    float m = fmaxf(fmaxf(ip[y * W + x], ip[y * W + x + 1]),
                    fmaxf(ip[(y + 1) * W + x], ip[(y + 1) * W + x + 1]));
    out[tid] = m;
}

// ---------------- cosine-similarity attention ----------------
// h2p/h1p: (B, C, Hs, Ws) pooled; attn out: (B*L + l ordering, Hs, Ws)
__global__ void attn_k(const float* __restrict__ h2p, const float* __restrict__ h1p,
                       const int* __restrict__ pts, float* __restrict__ attn,
                       int C, int Hs, int Ws, int shift) {
    int P = Hs * Ws;
    int tid = blockIdx.x * blockDim.x + threadIdx.x;
    int total = BB * LL * P;
    if (tid >= total) return;
    int p = tid % P;
    int bl = tid / P;       // b*L + l
    int b = bl / LL;

    int qr = pts[bl * 2 + 0] >> shift;
    int qc = pts[bl * 2 + 1] >> shift;
    int qidx = qr * Ws + qc;

    float dot = 0.f, n2 = 0.f, nq = 0.f;
    for (int c = 0; c < C; c++) {
        float v = h2p[(b * C + c) * P + p];
        float q = h1p[(b * C + c) * P + qidx];
        dot += v * q;
        n2 += v * v;
        nq += q * q;
    }
    float denom = fmaxf(sqrtf(n2), 1e-8f) * fmaxf(sqrtf(nq), 1e-8f);
    attn[tid] = dot / denom;
}

// ---------------- fused decoder layer ----------------
// out[n,co,y,x] = conv3x3(pad1) over channels [h2 upsampled (Ch2) | attn upsampled (1) | feat (Cf)]
// h2/attn live at half-res (Hin=Hout/2); feat at full res with src batch n%2.
// h2_mod: 1 for first layer (h2 is tiled encoder output -> src batch n%2), else 0.
__global__ void dec_conv_k(const float* __restrict__ h2, int h2_mod,
                           const float* __restrict__ attn, const float* __restrict__ feat,
                           const float* __restrict__ w, const float* __restrict__ bias,
                           float* __restrict__ out,
                           int Ch2, int Cf, int Co, int Hout, int Wout, int do_leaky) {
    const int N = BB * LL;
    int tid = blockIdx.x * blockDim.x + threadIdx.x;
    int total = N * Co * Hout * Wout;
    if (tid >= total) return;
    int x = tid % Wout;
    int y = (tid / Wout) % Hout;
    int co = (tid / (Wout * Hout)) % Co;
    int n = tid / (Wout * Hout * Co);

    int Hin = Hout >> 1, Win = Wout >> 1;
    int Cin = Ch2 + 1 + Cf;
    int nh2 = h2_mod ? (n % BB) : n;
    int nf = n % BB;

    const float* wco = w + co * Cin * 9;
    float acc = bias[co];
#pragma unroll
    for (int ky = 0; ky < 3; ky++) {
        int yy = y + ky - 1;
        if (yy < 0 || yy >= Hout) continue;
        int hy = yy >> 1;
#pragma unroll
        for (int kx = 0; kx < 3; kx++) {
            int xx = x + kx - 1;
            if (xx < 0 || xx >= Wout) continue;
            int hx = xx >> 1;
            const float* wk = wco + ky * 3 + kx;
            int hoff = hy * Win + hx;
            for (int ci = 0; ci < Ch2; ci++)
                acc += h2[(nh2 * Ch2 + ci) * Hin * Win + hoff] * wk[ci * 9];
            acc += attn[(n * Hin + hy) * Win + hx] * wk[Ch2 * 9];
            int foff = yy * Wout + xx;
            for (int cf = 0; cf < Cf; cf++)
                acc += feat[(nf * Cf + cf) * Hout * Wout + foff] * wk[(Ch2 + 1 + cf) * 9];
        }
    }
    out[tid] = do_leaky ? leaky(acc) : acc;
}

// ---------------- launch ----------------
extern "C" void kernel_launch(void* const* d_in, const int* in_sizes, int n_in,
                              void* d_out, int out_size) {
    const float* x1 = (const float*)d_in[0];
    const float* x2 = (const float*)d_in[1];
    const int* pts = (const int*)d_in[2];
    const float* ew[4] = {(const float*)d_in[3], (const float*)d_in[5],
                          (const float*)d_in[7], (const float*)d_in[9]};
    const float* eb[4] = {(const float*)d_in[4], (const float*)d_in[6],
                          (const float*)d_in[8], (const float*)d_in[10]};
    const float* dw[4] = {(const float*)d_in[11], (const float*)d_in[13],
                          (const float*)d_in[15], (const float*)d_in[17]};
    const float* db[4] = {(const float*)d_in[12], (const float*)d_in[14],
                          (const float*)d_in[16], (const float*)d_in[18]};
    float* out = (float*)d_out;

    float *h1p0, *h1p1, *h1p2, *h1p3;
    float *f0, *f1, *f2, *f3;
    float *h2p0, *h2p1, *h2p2, *h2p3;
    float *a0, *a1, *a2, *a3;
    float *dd0, *dd1, *dd2;
    cudaGetSymbolAddress((void**)&h1p0, g_h1p0);
    cudaGetSymbolAddress((void**)&h1p1, g_h1p1);
    cudaGetSymbolAddress((void**)&h1p2, g_h1p2);
    cudaGetSymbolAddress((void**)&h1p3, g_h1p3);
    cudaGetSymbolAddress((void**)&f0, g_f0);
    cudaGetSymbolAddress((void**)&f1, g_f1);
    cudaGetSymbolAddress((void**)&f2, g_f2);
    cudaGetSymbolAddress((void**)&f3, g_f3);
    cudaGetSymbolAddress((void**)&h2p0, g_h2p0);
    cudaGetSymbolAddress((void**)&h2p1, g_h2p1);
    cudaGetSymbolAddress((void**)&h2p2, g_h2p2);
    cudaGetSymbolAddress((void**)&h2p3, g_h2p3);
    cudaGetSymbolAddress((void**)&a0, g_attn0);
    cudaGetSymbolAddress((void**)&a1, g_attn1);
    cudaGetSymbolAddress((void**)&a2, g_attn2);
    cudaGetSymbolAddress((void**)&a3, g_attn3);
    cudaGetSymbolAddress((void**)&dd0, g_d0);
    cudaGetSymbolAddress((void**)&dd1, g_d1);
    cudaGetSymbolAddress((void**)&dd2, g_d2);

    const int T = 256;

    // ---- encoder level 0: 3->4 @256 ----
    conv5_leaky_k<<<cdiv(2*4*256*256, T), T>>>(x2, ew[0], eb[0], f0, 2, 3, 4, 256, 256);
    maxpool_k<<<cdiv(2*4*128*128, T), T>>>(f0, h2p0, 2*4, 256, 256);
    conv5_leaky_pool_k<<<cdiv(2*4*128*128, T), T>>>(x1, ew[0], eb[0], h1p0, 2, 3, 4, 256, 256);
    attn_k<<<cdiv(64*128*128, T), T>>>(h2p0, h1p0, pts, a0, 4, 128, 128, 1);

    // ---- encoder level 1: 4->8 @128 ----
    conv5_leaky_k<<<cdiv(2*8*128*128, T), T>>>(h2p0, ew[1], eb[1], f1, 2, 4, 8, 128, 128);
    maxpool_k<<<cdiv(2*8*64*64, T), T>>>(f1, h2p1, 2*8, 128, 128);
    conv5_leaky_pool_k<<<cdiv(2*8*64*64, T), T>>>(h1p0, ew[1], eb[1], h1p1, 2, 4, 8, 128, 128);
    attn_k<<<cdiv(64*64*64, T), T>>>(h2p1, h1p1, pts, a1, 8, 64, 64, 2);

    // ---- encoder level 2: 8->16 @64 ----
    conv5_leaky_k<<<cdiv(2*16*64*64, T), T>>>(h2p1, ew[2], eb[2], f2, 2, 8, 16, 64, 64);
    maxpool_k<<<cdiv(2*16*32*32, T), T>>>(f2, h2p2, 2*16, 64, 64);
    conv5_leaky_pool_k<<<cdiv(2*16*32*32, T), T>>>(h1p1, ew[2], eb[2], h1p2, 2, 8, 16, 64, 64);
    attn_k<<<cdiv(64*32*32, T), T>>>(h2p2, h1p2, pts, a2, 16, 32, 32, 3);

    // ---- encoder level 3: 16->16 @32 ----
    conv5_leaky_k<<<cdiv(2*16*32*32, T), T>>>(h2p2, ew[3], eb[3], f3, 2, 16, 16, 32, 32);
    maxpool_k<<<cdiv(2*16*16*16, T), T>>>(f3, h2p3, 2*16, 32, 32);
    conv5_leaky_pool_k<<<cdiv(2*16*16*16, T), T>>>(h1p2, ew[3], eb[3], h1p3, 2, 16, 16, 32, 32);
    attn_k<<<cdiv(64*16*16, T), T>>>(h2p3, h1p3, pts, a3, 16, 16, 16, 4);

    // ---- decoder (fused concat+upsample+concat+conv+leaky) ----
    // dec0: h2 (tiled enc, 16ch @16) + attn3 + feats[3](16ch @32) -> 16ch @32
    dec_conv_k<<<cdiv(64*16*32*32, T), T>>>(h2p3, 1, a3, f3, dw[0], db[0], dd0,
                                            16, 16, 16, 32, 32, 1);
    // dec1: dd0 (16ch @32) + attn2 + feats[2](16ch @64) -> 8ch @64
    dec_conv_k<<<cdiv(64*8*64*64, T), T>>>(dd0, 0, a2, f2, dw[1], db[1], dd1,
                                           16, 16, 8, 64, 64, 1);
    // dec2: dd1 (8ch @64) + attn1 + feats[1](8ch @128) -> 4ch @128
    dec_conv_k<<<cdiv(64*4*128*128, T), T>>>(dd1, 0, a1, f1, dw[2], db[2], dd2,
                                             8, 8, 4, 128, 128, 1);
    // dec3: dd2 (4ch @128) + attn0 + feats[0](4ch @256) -> 1ch @256, NO leaky
    dec_conv_k<<<cdiv(64*1*256*256, T), T>>>(dd2, 0, a0, f0, dw[3], db[3], out,
                                             4, 4, 1, 256, 256, 0);
}

// round 3
// speedup vs baseline: 4.4453x; 4.4453x over previous
#include <cuda_runtime.h>
#include <math.h>

#define BB 2
#define LL 32
#define NSLOPE 0.01f

// ---------------- scratch (static __device__, no allocs) ----------------
__device__ float g_h1p0[2*4*128*128];
__device__ float g_h1p1[2*8*64*64];
__device__ float g_h1p2[2*16*32*32];
__device__ float g_h1p3[2*16*16*16];

__device__ float g_f0[2*4*256*256];    // feats (pre-pool h2)
__device__ float g_f1[2*8*128*128];
__device__ float g_f2[2*16*64*64];
__device__ float g_f3[2*16*32*32];

__device__ float g_h2p0[2*4*128*128];  // pooled h2
__device__ float g_h2p1[2*8*64*64];
__device__ float g_h2p2[2*16*32*32];
__device__ float g_h2p3[2*16*16*16];

__device__ float g_attn0[64*128*128];  // (b*L+l, y, x)
__device__ float g_attn1[64*64*64];
__device__ float g_attn2[64*32*32];
__device__ float g_attn3[64*16*16];

__device__ float g_d0[64*16*32*32];
__device__ float g_d1[64*8*64*64];
__device__ float g_d2[64*4*128*128];

static inline int cdiv(int a, int b) { return (a + b - 1) / b; }

__device__ __forceinline__ float leaky(float v) { return v >= 0.f ? v : NSLOPE * v; }

// ============ encoder: fused conv5x5(pad2)+leaky[+write feats]+maxpool2 ============
// Each thread: one 2x2 pre-pool patch for COG output channels.
template<int CI, int CO, int COG, int H, bool WRITE_F>
__global__ void enc_conv_t(const float* __restrict__ in, const float* __restrict__ w,
                           const float* __restrict__ bias,
                           float* __restrict__ f, float* __restrict__ pooled) {
    constexpr int HP = H / 2;
    constexpr int NG = CO / COG;
    __shared__ float ws[COG * CI * 25];
    int bly = blockIdx.y;
    int cog = bly % NG;
    int n = bly / NG;
    int co0 = cog * COG;
    for (int i = threadIdx.x; i < COG * CI * 25; i += blockDim.x)
        ws[i] = w[co0 * CI * 25 + i];
    __syncthreads();

    int p = blockIdx.x * blockDim.x + threadIdx.x;
    if (p >= HP * HP) return;
    int px = p % HP, py = p / HP;

    float acc[COG][2][2];
#pragma unroll
    for (int g = 0; g < COG; g++) {
        float b = bias[co0 + g];
        acc[g][0][0] = b; acc[g][0][1] = b; acc[g][1][0] = b; acc[g][1][1] = b;
    }

    const float* ib = in + (size_t)n * CI * H * H;
#pragma unroll 1
    for (int ci = 0; ci < CI; ci++) {
        const float* src = ib + ci * H * H;
        float v[6][6];
#pragma unroll
        for (int r = 0; r < 6; r++) {
            int yy = 2 * py - 2 + r;
            bool oy = (unsigned)yy < (unsigned)H;
#pragma unroll
            for (int c = 0; c < 6; c++) {
                int xx = 2 * px - 2 + c;
                v[r][c] = (oy && (unsigned)xx < (unsigned)H) ? __ldg(src + yy * H + xx) : 0.f;
            }
        }
#pragma unroll
        for (int g = 0; g < COG; g++)
#pragma unroll
            for (int dy = 0; dy < 2; dy++)
#pragma unroll
                for (int dx = 0; dx < 2; dx++)
#pragma unroll
                    for (int ky = 0; ky < 5; ky++)
#pragma unroll
                        for (int kx = 0; kx < 5; kx++)
                            acc[g][dy][dx] += v[dy + ky][dx + kx] * ws[g * CI * 25 + ci * 25 + ky * 5 + kx];
    }

#pragma unroll
    for (int g = 0; g < COG; g++) {
        float a00 = leaky(acc[g][0][0]);
        float a01 = leaky(acc[g][0][1]);
        float a10 = leaky(acc[g][1][0]);
        float a11 = leaky(acc[g][1][1]);
        int coidx = n * CO + co0 + g;
        if (WRITE_F) {
            float* fp = f + (size_t)coidx * H * H;
            fp[(2 * py) * H + 2 * px] = a00;
            fp[(2 * py) * H + 2 * px + 1] = a01;
            fp[(2 * py + 1) * H + 2 * px] = a10;
            fp[(2 * py + 1) * H + 2 * px + 1] = a11;
        }
        pooled[((size_t)coidx * HP + py) * HP + px] = fmaxf(fmaxf(a00, a01), fmaxf(a10, a11));
    }
}

// ============ cosine-similarity attention ============
__global__ void attn_k(const float* __restrict__ h2p, const float* __restrict__ h1p,
                       const int* __restrict__ pts, float* __restrict__ attn,
                       int C, int Hs, int Ws, int shift) {
    int P = Hs * Ws;
    int tid = blockIdx.x * blockDim.x + threadIdx.x;
    int total = BB * LL * P;
    if (tid >= total) return;
    int p = tid % P;
    int bl = tid / P;
    int b = bl / LL;

    int qr = pts[bl * 2 + 0] >> shift;
    int qc = pts[bl * 2 + 1] >> shift;
    int qidx = qr * Ws + qc;

    float dot = 0.f, n2 = 0.f, nq = 0.f;
    for (int c = 0; c < C; c++) {
        float v = h2p[(b * C + c) * P + p];
        float q = h1p[(b * C + c) * P + qidx];
        dot += v * q;
        n2 += v * v;
        nq += q * q;
    }
    float denom = fmaxf(sqrtf(n2), 1e-8f) * fmaxf(sqrtf(nq), 1e-8f);
    attn[tid] = dot / denom;
}

// ============ fused decoder: concat + upsample2 + concat + conv3x3 + leaky ============
// Each thread: 2x2 output patch for COG output channels.
// Half-res inputs (h2, attn) read with >>1 indexing; full-res feat read direct.
template<int CH2, int CF, int CO, int COG, int HO, bool LEAKY, bool H2MOD>
__global__ void dec_conv_t(const float* __restrict__ h2, const float* __restrict__ attn,
                           const float* __restrict__ feat, const float* __restrict__ w,
                           const float* __restrict__ bias, float* __restrict__ out) {
    constexpr int CIN = CH2 + 1 + CF;
    constexpr int HH = HO / 2;
    constexpr int NG = CO / COG;
    __shared__ float ws[COG * CIN * 9];
    int bly = blockIdx.y;
    int cog = bly % NG;
    int n = bly / NG;
    int co0 = cog * COG;
    for (int i = threadIdx.x; i < COG * CIN * 9; i += blockDim.x)
        ws[i] = w[co0 * CIN * 9 + i];
    __syncthreads();

    int p = blockIdx.x * blockDim.x + threadIdx.x;
    if (p >= HH * HH) return;
    int X = p % HH, Y = p / HH;
    int nh2 = H2MOD ? (n % BB) : n;
    int nf = n % BB;

    float acc[COG][2][2];
#pragma unroll
    for (int g = 0; g < COG; g++) {
        float b = bias[co0 + g];
        acc[g][0][0] = b; acc[g][0][1] = b; acc[g][1][0] = b; acc[g][1][1] = b;
    }

    // ---- half-res channels: CH2 of h2, then 1 of attn ----
    {
        const float* hb = h2 + (size_t)nh2 * CH2 * HH * HH;
#pragma unroll 1
        for (int ci = 0; ci < CH2; ci++) {
            const float* src = hb + ci * HH * HH;
            float v[3][3];
#pragma unroll
            for (int r = 0; r < 3; r++) {
                int hy = Y - 1 + r;
                bool oy = (unsigned)hy < (unsigned)HH;
#pragma unroll
                for (int c = 0; c < 3; c++) {
                    int hx = X - 1 + c;
                    v[r][c] = (oy && (unsigned)hx < (unsigned)HH) ? __ldg(src + hy * HH + hx) : 0.f;
                }
            }
#pragma unroll
            for (int g = 0; g < COG; g++)
#pragma unroll
                for (int dy = 0; dy < 2; dy++)
#pragma unroll
                    for (int dx = 0; dx < 2; dx++)
#pragma unroll
                        for (int ky = 0; ky < 3; ky++)
#pragma unroll
                            for (int kx = 0; kx < 3; kx++)
                                acc[g][dy][dx] += v[((dy + ky - 1) >> 1) + 1][((dx + kx - 1) >> 1) + 1]
                                                  * ws[g * CIN * 9 + ci * 9 + ky * 3 + kx];
        }
        // attn channel (index CH2), batch index n (not modded)
        {
            const float* src = attn + (size_t)n * HH * HH;
            float v[3][3];
#pragma unroll
            for (int r = 0; r < 3; r++) {
                int hy = Y - 1 + r;
                bool oy = (unsigned)hy < (unsigned)HH;
#pragma unroll
                for (int c = 0; c < 3; c++) {
                    int hx = X - 1 + c;
                    v[r][c] = (oy && (unsigned)hx < (unsigned)HH) ? __ldg(src + hy * HH + hx) : 0.f;
                }
            }
#pragma unroll
            for (int g = 0; g < COG; g++)
#pragma unroll
                for (int dy = 0; dy < 2; dy++)
#pragma unroll
                    for (int dx = 0; dx < 2; dx++)
#pragma unroll
                        for (int ky = 0; ky < 3; ky++)
#pragma unroll
                            for (int kx = 0; kx < 3; kx++)
                                acc[g][dy][dx] += v[((dy + ky - 1) >> 1) + 1][((dx + kx - 1) >> 1) + 1]
                                                  * ws[g * CIN * 9 + CH2 * 9 + ky * 3 + kx];
        }
    }

    // ---- full-res feat channels ----
    {
        const float* fb = feat + (size_t)nf * CF * HO * HO;
#pragma unroll 1
        for (int cf = 0; cf < CF; cf++) {
            const float* src = fb + cf * HO * HO;
            float v[4][4];
#pragma unroll
            for (int r = 0; r < 4; r++) {
                int yy = 2 * Y - 1 + r;
                bool oy = (unsigned)yy < (unsigned)HO;
#pragma unroll
                for (int c = 0; c < 4; c++) {
                    int xx = 2 * X - 1 + c;
                    v[r][c] = (oy && (unsigned)xx < (unsigned)HO) ? __ldg(src + yy * HO + xx) : 0.f;
                }
            }
#pragma unroll
            for (int g = 0; g < COG; g++)
#pragma unroll
                for (int dy = 0; dy < 2; dy++)
#pragma unroll
                    for (int dx = 0; dx < 2; dx++)
#pragma unroll
                        for (int ky = 0; ky < 3; ky++)
#pragma unroll
                            for (int kx = 0; kx < 3; kx++)
                                acc[g][dy][dx] += v[dy + ky][dx + kx]
                                                  * ws[g * CIN * 9 + (CH2 + 1 + cf) * 9 + ky * 3 + kx];
        }
    }

#pragma unroll
    for (int g = 0; g < COG; g++)
#pragma unroll
        for (int dy = 0; dy < 2; dy++)
#pragma unroll
            for (int dx = 0; dx < 2; dx++) {
                float r = acc[g][dy][dx];
                if (LEAKY) r = leaky(r);
                out[(((size_t)n * CO + co0 + g) * HO + 2 * Y + dy) * HO + 2 * X + dx] = r;
            }
}

// ---------------- launch ----------------
extern "C" void kernel_launch(void* const* d_in, const int* in_sizes, int n_in,
                              void* d_out, int out_size) {
    const float* x1 = (const float*)d_in[0];
    const float* x2 = (const float*)d_in[1];
    const int* pts = (const int*)d_in[2];
    const float* ew[4] = {(const float*)d_in[3], (const float*)d_in[5],
                          (const float*)d_in[7], (const float*)d_in[9]};
    const float* eb[4] = {(const float*)d_in[4], (const float*)d_in[6],
                          (const float*)d_in[8], (const float*)d_in[10]};
    const float* dw[4] = {(const float*)d_in[11], (const float*)d_in[13],
                          (const float*)d_in[15], (const float*)d_in[17]};
    const float* db[4] = {(const float*)d_in[12], (const float*)d_in[14],
                          (const float*)d_in[16], (const float*)d_in[18]};
    float* out = (float*)d_out;

    float *h1p0, *h1p1, *h1p2, *h1p3;
    float *f0, *f1, *f2, *f3;
    float *h2p0, *h2p1, *h2p2, *h2p3;
    float *a0, *a1, *a2, *a3;
    float *dd0, *dd1, *dd2;
    cudaGetSymbolAddress((void**)&h1p0, g_h1p0);
    cudaGetSymbolAddress((void**)&h1p1, g_h1p1);
    cudaGetSymbolAddress((void**)&h1p2, g_h1p2);
    cudaGetSymbolAddress((void**)&h1p3, g_h1p3);
    cudaGetSymbolAddress((void**)&f0, g_f0);
    cudaGetSymbolAddress((void**)&f1, g_f1);
    cudaGetSymbolAddress((void**)&f2, g_f2);
    cudaGetSymbolAddress((void**)&f3, g_f3);
    cudaGetSymbolAddress((void**)&h2p0, g_h2p0);
    cudaGetSymbolAddress((void**)&h2p1, g_h2p1);
    cudaGetSymbolAddress((void**)&h2p2, g_h2p2);
    cudaGetSymbolAddress((void**)&h2p3, g_h2p3);
    cudaGetSymbolAddress((void**)&a0, g_attn0);
    cudaGetSymbolAddress((void**)&a1, g_attn1);
    cudaGetSymbolAddress((void**)&a2, g_attn2);
    cudaGetSymbolAddress((void**)&a3, g_attn3);
    cudaGetSymbolAddress((void**)&dd0, g_d0);
    cudaGetSymbolAddress((void**)&dd1, g_d1);
    cudaGetSymbolAddress((void**)&dd2, g_d2);

    const int T = 128;

    // ---- encoder level 0: 3->4 @256 (COG=4, NG=1) ----
    {
        dim3 g0(cdiv(128 * 128, T), 2 * 1);
        enc_conv_t<3, 4, 4, 256, true><<<g0, T>>>(x2, ew[0], eb[0], f0, h2p0);   // h2 path
        enc_conv_t<3, 4, 4, 256, false><<<g0, T>>>(x1, ew[0], eb[0], nullptr, h1p0); // h1 path
    }
    attn_k<<<cdiv(64 * 128 * 128, 256), 256>>>(h2p0, h1p0, pts, a0, 4, 128, 128, 1);

    // ---- encoder level 1: 4->8 @128 (COG=4, NG=2) ----
    {
        dim3 g1(cdiv(64 * 64, T), 2 * 2);
        enc_conv_t<4, 8, 4, 128, true><<<g1, T>>>(h2p0, ew[1], eb[1], f1, h2p1);
        enc_conv_t<4, 8, 4, 128, false><<<g1, T>>>(h1p0, ew[1], eb[1], nullptr, h1p1);
    }
    attn_k<<<cdiv(64 * 64 * 64, 256), 256>>>(h2p1, h1p1, pts, a1, 8, 64, 64, 2);

    // ---- encoder level 2: 8->16 @64 (COG=4, NG=4) ----
    {
        dim3 g2(cdiv(32 * 32, T), 2 * 4);
        enc_conv_t<8, 16, 4, 64, true><<<g2, T>>>(h2p1, ew[2], eb[2], f2, h2p2);
        enc_conv_t<8, 16, 4, 64, false><<<g2, T>>>(h1p1, ew[2], eb[2], nullptr, h1p2);
    }
    attn_k<<<cdiv(64 * 32 * 32, 256), 256>>>(h2p2, h1p2, pts, a2, 16, 32, 32, 3);

    // ---- encoder level 3: 16->16 @32 (COG=4, NG=4) ----
    {
        dim3 g3(cdiv(16 * 16, T), 2 * 4);
        enc_conv_t<16, 16, 4, 32, true><<<g3, T>>>(h2p2, ew[3], eb[3], f3, h2p3);
        enc_conv_t<16, 16, 4, 32, false><<<g3, T>>>(h1p2, ew[3], eb[3], nullptr, h1p3);
    }
    attn_k<<<cdiv(64 * 16 * 16, 256), 256>>>(h2p3, h1p3, pts, a3, 16, 16, 16, 4);

    // ---- decoder ----
    // dec0: h2p3 (16ch @16, tiled->n%B) + attn3 + f3(16ch @32) -> 16ch @32
    {
        dim3 g(cdiv(16 * 16, T), 64 * 4);
        dec_conv_t<16, 16, 16, 4, 32, true, true><<<g, T>>>(h2p3, a3, f3, dw[0], db[0], dd0);
    }
    // dec1: dd0 (16ch @32) + attn2 + f2(16ch @64) -> 8ch @64
    {
        dim3 g(cdiv(32 * 32, T), 64 * 2);
        dec_conv_t<16, 16, 8, 4, 64, true, false><<<g, T>>>(dd0, a2, f2, dw[1], db[1], dd1);
    }
    // dec2: dd1 (8ch @64) + attn1 + f1(8ch @128) -> 4ch @128
    {
        dim3 g(cdiv(64 * 64, T), 64 * 1);
        dec_conv_t<8, 8, 4, 4, 128, true, false><<<g, T>>>(dd1, a1, f1, dw[2], db[2], dd2);
    }
    // dec3: dd2 (4ch @128) + attn0 + f0(4ch @256) -> 1ch @256, NO leaky
    {
        dim3 g(cdiv(128 * 128, T), 64 * 1);
        dec_conv_t<4, 4, 1, 1, 256, false, false><<<g, T>>>(dd2, a0, f0, dw[3], db[3], out);
    }
}

// round 4
// speedup vs baseline: 5.5238x; 1.2426x over previous
#include <cuda_runtime.h>
#include <math.h>

#define BB 2
#define LL 32
#define NSLOPE 0.01f

// ---------------- scratch (static __device__, no allocs) ----------------
__device__ float g_h1p0[2*4*128*128];
__device__ float g_h1p1[2*8*64*64];
__device__ float g_h1p2[2*16*32*32];
__device__ float g_h1p3[2*16*16*16];

__device__ float g_f0[2*4*256*256];    // feats (pre-pool h2)
__device__ float g_f1[2*8*128*128];
__device__ float g_f2[2*16*64*64];
__device__ float g_f3[2*16*32*32];

__device__ float g_h2p0[2*4*128*128];  // pooled h2
__device__ float g_h2p1[2*8*64*64];
__device__ float g_h2p2[2*16*32*32];
__device__ float g_h2p3[2*16*16*16];

__device__ float g_attn0[64*128*128];  // (b*L+l, y, x)
__device__ float g_attn1[64*64*64];
__device__ float g_attn2[64*32*32];
__device__ float g_attn3[64*16*16];

__device__ float g_d0[64*16*32*32];
__device__ float g_d1[64*8*64*64];
__device__ float g_d2[64*4*128*128];

static inline int cdiv(int a, int b) { return (a + b - 1) / b; }

__device__ __forceinline__ float leaky(float v) { return v >= 0.f ? v : NSLOPE * v; }

// ============ encoder: both paths in one launch (z=0: h2/x2, z=1: h1/x1) ============
// fused conv5x5(pad2)+leaky[+feats]+maxpool2. Thread: 2x2 pre-pool patch, COG out chans.
template<int CI, int CO, int COG, int H>
__global__ void enc_conv2_t(const float* __restrict__ in2, const float* __restrict__ in1,
                            const float* __restrict__ w, const float* __restrict__ bias,
                            float* __restrict__ f, float* __restrict__ pooled2,
                            float* __restrict__ pooled1) {
    constexpr int HP = H / 2;
    constexpr int NG = CO / COG;
    __shared__ float ws[COG * CI * 25];
    int bly = blockIdx.y;
    int cog = bly % NG;
    int n = bly / NG;
    int co0 = cog * COG;
    bool path2 = (blockIdx.z == 0);
    const float* in = path2 ? in2 : in1;
    float* pooled = path2 ? pooled2 : pooled1;

    for (int i = threadIdx.x; i < COG * CI * 25; i += blockDim.x)
        ws[i] = w[co0 * CI * 25 + i];
    __syncthreads();

    int p = blockIdx.x * blockDim.x + threadIdx.x;
    if (p >= HP * HP) return;
    int px = p % HP, py = p / HP;

    float acc[COG][2][2];
#pragma unroll
    for (int g = 0; g < COG; g++) {
        float b = bias[co0 + g];
        acc[g][0][0] = b; acc[g][0][1] = b; acc[g][1][0] = b; acc[g][1][1] = b;
    }

    const float* ib = in + (size_t)n * CI * H * H;
#pragma unroll 2
    for (int ci = 0; ci < CI; ci++) {
        const float* src = ib + ci * H * H;
        float v[6][6];
#pragma unroll
        for (int r = 0; r < 6; r++) {
            int yy = 2 * py - 2 + r;
            bool oy = (unsigned)yy < (unsigned)H;
#pragma unroll
            for (int c = 0; c < 6; c++) {
                int xx = 2 * px - 2 + c;
                v[r][c] = (oy && (unsigned)xx < (unsigned)H) ? __ldg(src + yy * H + xx) : 0.f;
            }
        }
#pragma unroll
        for (int g = 0; g < COG; g++)
#pragma unroll
            for (int dy = 0; dy < 2; dy++)
#pragma unroll
                for (int dx = 0; dx < 2; dx++)
#pragma unroll
                    for (int ky = 0; ky < 5; ky++)
#pragma unroll
                        for (int kx = 0; kx < 5; kx++)
                            acc[g][dy][dx] += v[dy + ky][dx + kx] * ws[g * CI * 25 + ci * 25 + ky * 5 + kx];
    }

#pragma unroll
    for (int g = 0; g < COG; g++) {
        float a00 = leaky(acc[g][0][0]);
        float a01 = leaky(acc[g][0][1]);
        float a10 = leaky(acc[g][1][0]);
        float a11 = leaky(acc[g][1][1]);
        int coidx = n * CO + co0 + g;
        if (path2) {
            float* fp = f + (size_t)coidx * H * H;
            fp[(2 * py) * H + 2 * px] = a00;
            fp[(2 * py) * H + 2 * px + 1] = a01;
            fp[(2 * py + 1) * H + 2 * px] = a10;
            fp[(2 * py + 1) * H + 2 * px + 1] = a11;
        }
        pooled[((size_t)coidx * HP + py) * HP + px] = fmaxf(fmaxf(a00, a01), fmaxf(a10, a11));
    }
}

// ============ cosine-similarity attention: one v-load serves all L queries ============
// grid: (cdiv(P,T), B). smem: queries (L*C) + query-norms (L).
template<int C, int HS, int SHIFT>
__global__ void attn2_t(const float* __restrict__ h2p, const float* __restrict__ h1p,
                        const int* __restrict__ pts, float* __restrict__ attn) {
    constexpr int P = HS * HS;
    __shared__ float qs[LL * C];
    __shared__ float nqs[LL];
    int b = blockIdx.y;
    int tid = threadIdx.x;

    for (int i = tid; i < LL * C; i += blockDim.x) {
        int l = i / C, c = i % C;
        int qr = pts[(b * LL + l) * 2 + 0] >> SHIFT;
        int qc = pts[(b * LL + l) * 2 + 1] >> SHIFT;
        qs[l * C + c] = h1p[((size_t)(b * C + c)) * P + qr * HS + qc];
    }
    __syncthreads();
    if (tid < LL) {
        float s = 0.f;
#pragma unroll
        for (int c = 0; c < C; c++) s += qs[tid * C + c] * qs[tid * C + c];
        nqs[tid] = fmaxf(sqrtf(s), 1e-8f);
    }
    __syncthreads();

    int p = blockIdx.x * blockDim.x + tid;
    if (p >= P) return;
    float v[C];
    float n2 = 0.f;
#pragma unroll
    for (int c = 0; c < C; c++) {
        v[c] = h2p[((size_t)(b * C + c)) * P + p];
        n2 += v[c] * v[c];
    }
    float inv2 = 1.f / fmaxf(sqrtf(n2), 1e-8f);
#pragma unroll
    for (int l = 0; l < LL; l++) {
        float dot = 0.f;
#pragma unroll
        for (int c = 0; c < C; c++) dot += v[c] * qs[l * C + c];
        attn[((size_t)(b * LL + l)) * P + p] = dot * inv2 / nqs[l];
    }
}

// ============ fused decoder: concat + upsample2 + concat + conv3x3 + leaky ============
template<int CH2, int CF, int CO, int COG, int HO, bool LEAKY, bool H2MOD>
__global__ void dec_conv_t(const float* __restrict__ h2, const float* __restrict__ attn,
                           const float* __restrict__ feat, const float* __restrict__ w,
                           const float* __restrict__ bias, float* __restrict__ out) {
    constexpr int CIN = CH2 + 1 + CF;
    constexpr int HH = HO / 2;
    constexpr int NG = CO / COG;
    __shared__ float ws[COG * CIN * 9];
    int bly = blockIdx.y;
    int cog = bly % NG;
    int n = bly / NG;
    int co0 = cog * COG;
    for (int i = threadIdx.x; i < COG * CIN * 9; i += blockDim.x)
        ws[i] = w[co0 * CIN * 9 + i];
    __syncthreads();

    int p = blockIdx.x * blockDim.x + threadIdx.x;
    if (p >= HH * HH) return;
    int X = p % HH, Y = p / HH;
    int nh2 = H2MOD ? (n % BB) : n;
    int nf = n % BB;

    float acc[COG][2][2];
#pragma unroll
    for (int g = 0; g < COG; g++) {
        float b = bias[co0 + g];
        acc[g][0][0] = b; acc[g][0][1] = b; acc[g][1][0] = b; acc[g][1][1] = b;
    }

    // ---- half-res channels: CH2 of h2, then 1 of attn ----
    {
        const float* hb = h2 + (size_t)nh2 * CH2 * HH * HH;
#pragma unroll 2
        for (int ci = 0; ci < CH2; ci++) {
            const float* src = hb + ci * HH * HH;
            float v[3][3];
#pragma unroll
            for (int r = 0; r < 3; r++) {
                int hy = Y - 1 + r;
                bool oy = (unsigned)hy < (unsigned)HH;
#pragma unroll
                for (int c = 0; c < 3; c++) {
                    int hx = X - 1 + c;
                    v[r][c] = (oy && (unsigned)hx < (unsigned)HH) ? __ldg(src + hy * HH + hx) : 0.f;
                }
            }
#pragma unroll
            for (int g = 0; g < COG; g++)
#pragma unroll
                for (int dy = 0; dy < 2; dy++)
#pragma unroll
                    for (int dx = 0; dx < 2; dx++)
#pragma unroll
                        for (int ky = 0; ky < 3; ky++)
#pragma unroll
                            for (int kx = 0; kx < 3; kx++)
                                acc[g][dy][dx] += v[((dy + ky - 1) >> 1) + 1][((dx + kx - 1) >> 1) + 1]
                                                  * ws[g * CIN * 9 + ci * 9 + ky * 3 + kx];
        }
        // attn channel (index CH2), batch index n (not modded)
        {
            const float* src = attn + (size_t)n * HH * HH;
            float v[3][3];
#pragma unroll
            for (int r = 0; r < 3; r++) {
                int hy = Y - 1 + r;
                bool oy = (unsigned)hy < (unsigned)HH;
#pragma unroll
                for (int c = 0; c < 3; c++) {
                    int hx = X - 1 + c;
                    v[r][c] = (oy && (unsigned)hx < (unsigned)HH) ? __ldg(src + hy * HH + hx) : 0.f;
                }
            }
#pragma unroll
            for (int g = 0; g < COG; g++)
#pragma unroll
                for (int dy = 0; dy < 2; dy++)
#pragma unroll
                    for (int dx = 0; dx < 2; dx++)
#pragma unroll
                        for (int ky = 0; ky < 3; ky++)
#pragma unroll
                            for (int kx = 0; kx < 3; kx++)
                                acc[g][dy][dx] += v[((dy + ky - 1) >> 1) + 1][((dx + kx - 1) >> 1) + 1]
                                                  * ws[g * CIN * 9 + CH2 * 9 + ky * 3 + kx];
        }
    }

    // ---- full-res feat channels ----
    {
        const float* fb = feat + (size_t)nf * CF * HO * HO;
#pragma unroll 2
        for (int cf = 0; cf < CF; cf++) {
            const float* src = fb + cf * HO * HO;
            float v[4][4];
#pragma unroll
            for (int r = 0; r < 4; r++) {
                int yy = 2 * Y - 1 + r;
                bool oy = (unsigned)yy < (unsigned)HO;
#pragma unroll
                for (int c = 0; c < 4; c++) {
                    int xx = 2 * X - 1 + c;
                    v[r][c] = (oy && (unsigned)xx < (unsigned)HO) ? __ldg(src + yy * HO + xx) : 0.f;
                }
            }
#pragma unroll
            for (int g = 0; g < COG; g++)
#pragma unroll
                for (int dy = 0; dy < 2; dy++)
#pragma unroll
                    for (int dx = 0; dx < 2; dx++)
#pragma unroll
                        for (int ky = 0; ky < 3; ky++)
#pragma unroll
                            for (int kx = 0; kx < 3; kx++)
                                acc[g][dy][dx] += v[dy + ky][dx + kx]
                                                  * ws[g * CIN * 9 + (CH2 + 1 + cf) * 9 + ky * 3 + kx];
        }
    }

#pragma unroll
    for (int g = 0; g < COG; g++)
#pragma unroll
        for (int dy = 0; dy < 2; dy++)
#pragma unroll
            for (int dx = 0; dx < 2; dx++) {
                float r = acc[g][dy][dx];
                if (LEAKY) r = leaky(r);
                out[(((size_t)n * CO + co0 + g) * HO + 2 * Y + dy) * HO + 2 * X + dx] = r;
            }
}

// ---------------- launch ----------------
extern "C" void kernel_launch(void* const* d_in, const int* in_sizes, int n_in,
                              void* d_out, int out_size) {
    const float* x1 = (const float*)d_in[0];
    const float* x2 = (const float*)d_in[1];
    const int* pts = (const int*)d_in[2];
    const float* ew[4] = {(const float*)d_in[3], (const float*)d_in[5],
                          (const float*)d_in[7], (const float*)d_in[9]};
    const float* eb[4] = {(const float*)d_in[4], (const float*)d_in[6],
                          (const float*)d_in[8], (const float*)d_in[10]};
    const float* dw[4] = {(const float*)d_in[11], (const float*)d_in[13],
                          (const float*)d_in[15], (const float*)d_in[17]};
    const float* db[4] = {(const float*)d_in[12], (const float*)d_in[14],
                          (const float*)d_in[16], (const float*)d_in[18]};
    float* out = (float*)d_out;

    float *h1p0, *h1p1, *h1p2, *h1p3;
    float *f0, *f1, *f2, *f3;
    float *h2p0, *h2p1, *h2p2, *h2p3;
    float *a0, *a1, *a2, *a3;
    float *dd0, *dd1, *dd2;
    cudaGetSymbolAddress((void**)&h1p0, g_h1p0);
    cudaGetSymbolAddress((void**)&h1p1, g_h1p1);
    cudaGetSymbolAddress((void**)&h1p2, g_h1p2);
    cudaGetSymbolAddress((void**)&h1p3, g_h1p3);
    cudaGetSymbolAddress((void**)&f0, g_f0);
    cudaGetSymbolAddress((void**)&f1, g_f1);
    cudaGetSymbolAddress((void**)&f2, g_f2);
    cudaGetSymbolAddress((void**)&f3, g_f3);
    cudaGetSymbolAddress((void**)&h2p0, g_h2p0);
    cudaGetSymbolAddress((void**)&h2p1, g_h2p1);
    cudaGetSymbolAddress((void**)&h2p2, g_h2p2);
    cudaGetSymbolAddress((void**)&h2p3, g_h2p3);
    cudaGetSymbolAddress((void**)&a0, g_attn0);
    cudaGetSymbolAddress((void**)&a1, g_attn1);
    cudaGetSymbolAddress((void**)&a2, g_attn2);
    cudaGetSymbolAddress((void**)&a3, g_attn3);
    cudaGetSymbolAddress((void**)&dd0, g_d0);
    cudaGetSymbolAddress((void**)&dd1, g_d1);
    cudaGetSymbolAddress((void**)&dd2, g_d2);

    const int T = 128;

    // ---- encoder (both paths per launch) ----
    enc_conv2_t<3, 4, 4, 256><<<dim3(cdiv(128*128, T), 2*1, 2), T>>>(x2, x1, ew[0], eb[0], f0, h2p0, h1p0);
    attn2_t<4, 128, 1><<<dim3(cdiv(128*128, 256), BB), 256>>>(h2p0, h1p0, pts, a0);

    enc_conv2_t<4, 8, 4, 128><<<dim3(cdiv(64*64, T), 2*2, 2), T>>>(h2p0, h1p0, ew[1], eb[1], f1, h2p1, h1p1);
    attn2_t<8, 64, 2><<<dim3(cdiv(64*64, 256), BB), 256>>>(h2p1, h1p1, pts, a1);

    enc_conv2_t<8, 16, 4, 64><<<dim3(cdiv(32*32, T), 2*4, 2), T>>>(h2p1, h1p1, ew[2], eb[2], f2, h2p2, h1p2);
    attn2_t<16, 32, 3><<<dim3(cdiv(32*32, 256), BB), 256>>>(h2p2, h1p2, pts, a2);

    enc_conv2_t<16, 16, 4, 32><<<dim3(cdiv(16*16, T), 2*4, 2), T>>>(h2p2, h1p2, ew[3], eb[3], f3, h2p3, h1p3);
    attn2_t<16, 16, 4><<<dim3(cdiv(16*16, 256), BB), 256>>>(h2p3, h1p3, pts, a3);

    // ---- decoder ----
    // dec0: h2p3 (16ch @16, tiled->n%B) + attn3 + f3(16ch @32) -> 16ch @32
    dec_conv_t<16, 16, 16, 4, 32, true, true><<<dim3(cdiv(16*16, T), 64*4), T>>>(h2p3, a3, f3, dw[0], db[0], dd0);
    // dec1: dd0 (16ch @32) + attn2 + f2(16ch @64) -> 8ch @64
    dec_conv_t<16, 16, 8, 4, 64, true, false><<<dim3(cdiv(32*32, T), 64*2), T>>>(dd0, a2, f2, dw[1], db[1], dd1);
    // dec2: dd1 (8ch @64) + attn1 + f1(8ch @128) -> 4ch @128
    dec_conv_t<8, 8, 4, 4, 128, true, false><<<dim3(cdiv(64*64, T), 64*1), T>>>(dd1, a1, f1, dw[2], db[2], dd2);
    // dec3: dd2 (4ch @128) + attn0 + f0(4ch @256) -> 1ch @256, NO leaky
    dec_conv_t<4, 4, 1, 1, 256, false, false><<<dim3(cdiv(128*128, T), 64*1), T>>>(dd2, a0, f0, dw[3], db[3], out);
}

// round 5
// speedup vs baseline: 6.2894x; 1.1386x over previous
#include <cuda_runtime.h>
#include <math.h>

#define BB 2
#define LL 32
#define NSLOPE 0.01f

// ---------------- scratch (static __device__, no allocs) ----------------
__device__ float g_h1p0[2*4*128*128];
__device__ float g_h1p1[2*8*64*64];
__device__ float g_h1p2[2*16*32*32];
__device__ float g_h1p3[2*16*16*16];

__device__ float g_f0[2*4*256*256];    // feats (pre-pool h2)
__device__ float g_f1[2*8*128*128];
__device__ float g_f2[2*16*64*64];
__device__ float g_f3[2*16*32*32];

__device__ float g_h2p0[2*4*128*128];  // pooled h2
__device__ float g_h2p1[2*8*64*64];
__device__ float g_h2p2[2*16*32*32];
__device__ float g_h2p3[2*16*16*16];

__device__ float g_attn0[64*128*128];  // (b*L+l, y, x)
__device__ float g_attn1[64*64*64];
__device__ float g_attn2[64*32*32];
__device__ float g_attn3[64*16*16];

__device__ float g_d0[64*16*32*32];
__device__ float g_d1[64*8*64*64];
__device__ float g_d2[64*4*128*128];

static inline int cdiv(int a, int b) { return (a + b - 1) / b; }

__device__ __forceinline__ float leaky(float v) { return v >= 0.f ? v : NSLOPE * v; }

// ============ encoder: both paths in one launch (z=0: h2/x2, z=1: h1/x1) ============
template<int CI, int CO, int COG, int H>
__global__ void enc_conv2_t(const float* __restrict__ in2, const float* __restrict__ in1,
                            const float* __restrict__ w, const float* __restrict__ bias,
                            float* __restrict__ f, float* __restrict__ pooled2,
                            float* __restrict__ pooled1) {
    constexpr int HP = H / 2;
    constexpr int NG = CO / COG;
    __shared__ float ws[COG * CI * 25];
    int bly = blockIdx.y;
    int cog = bly % NG;
    int n = bly / NG;
    int co0 = cog * COG;
    bool path2 = (blockIdx.z == 0);
    const float* in = path2 ? in2 : in1;
    float* pooled = path2 ? pooled2 : pooled1;

    for (int i = threadIdx.x; i < COG * CI * 25; i += blockDim.x)
        ws[i] = w[co0 * CI * 25 + i];
    __syncthreads();

    int p = blockIdx.x * blockDim.x + threadIdx.x;
    if (p >= HP * HP) return;
    int px = p % HP, py = p / HP;

    float acc[COG][2][2];
#pragma unroll
    for (int g = 0; g < COG; g++) {
        float b = bias[co0 + g];
        acc[g][0][0] = b; acc[g][0][1] = b; acc[g][1][0] = b; acc[g][1][1] = b;
    }

    const float* ib = in + (size_t)n * CI * H * H;
#pragma unroll 4
    for (int ci = 0; ci < CI; ci++) {
        const float* src = ib + ci * H * H;
        float v[6][6];
#pragma unroll
        for (int r = 0; r < 6; r++) {
            int yy = 2 * py - 2 + r;
            bool oy = (unsigned)yy < (unsigned)H;
#pragma unroll
            for (int c = 0; c < 6; c++) {
                int xx = 2 * px - 2 + c;
                v[r][c] = (oy && (unsigned)xx < (unsigned)H) ? __ldg(src + yy * H + xx) : 0.f;
            }
        }
#pragma unroll
        for (int g = 0; g < COG; g++)
#pragma unroll
            for (int dy = 0; dy < 2; dy++)
#pragma unroll
                for (int dx = 0; dx < 2; dx++)
#pragma unroll
                    for (int ky = 0; ky < 5; ky++)
#pragma unroll
                        for (int kx = 0; kx < 5; kx++)
                            acc[g][dy][dx] += v[dy + ky][dx + kx] * ws[g * CI * 25 + ci * 25 + ky * 5 + kx];
    }

#pragma unroll
    for (int g = 0; g < COG; g++) {
        float a00 = leaky(acc[g][0][0]);
        float a01 = leaky(acc[g][0][1]);
        float a10 = leaky(acc[g][1][0]);
        float a11 = leaky(acc[g][1][1]);
        int coidx = n * CO + co0 + g;
        if (path2) {
            float* fp = f + (size_t)coidx * H * H;
            fp[(2 * py) * H + 2 * px] = a00;
            fp[(2 * py) * H + 2 * px + 1] = a01;
            fp[(2 * py + 1) * H + 2 * px] = a10;
            fp[(2 * py + 1) * H + 2 * px + 1] = a11;
        }
        pooled[((size_t)coidx * HP + py) * HP + px] = fmaxf(fmaxf(a00, a01), fmaxf(a10, a11));
    }
}

// ============ attention, all 4 levels in one kernel ============
// Each thread: 4 consecutive pixels (float4), all 32 queries.
template<int C, int HS, int SHIFT>
__device__ __forceinline__ void attn_level(const float* __restrict__ h2p,
                                           const float* __restrict__ h1p,
                                           const int* __restrict__ pts,
                                           float* __restrict__ attn,
                                           int b, int blk, float* qs, float* nqs) {
    constexpr int P = HS * HS;
    int tid = threadIdx.x;
    for (int i = tid; i < LL * C; i += blockDim.x) {
        int l = i / C, c = i % C;
        int qr = pts[(b * LL + l) * 2 + 0] >> SHIFT;
        int qc = pts[(b * LL + l) * 2 + 1] >> SHIFT;
        qs[l * C + c] = h1p[((size_t)(b * C + c)) * P + qr * HS + qc];
    }
    __syncthreads();
    if (tid < LL) {
        float s = 0.f;
#pragma unroll
        for (int c = 0; c < C; c++) s += qs[tid * C + c] * qs[tid * C + c];
        nqs[tid] = fmaxf(sqrtf(s), 1e-8f);
    }
    __syncthreads();

    int p0 = (blk * (int)blockDim.x + tid) * 4;
    if (p0 >= P) return;
    float4 v[C];
    float4 n2 = make_float4(0.f, 0.f, 0.f, 0.f);
#pragma unroll
    for (int c = 0; c < C; c++) {
        v[c] = *(const float4*)(h2p + ((size_t)(b * C + c)) * P + p0);
        n2.x += v[c].x * v[c].x; n2.y += v[c].y * v[c].y;
        n2.z += v[c].z * v[c].z; n2.w += v[c].w * v[c].w;
    }
    float4 inv;
    inv.x = 1.f / fmaxf(sqrtf(n2.x), 1e-8f);
    inv.y = 1.f / fmaxf(sqrtf(n2.y), 1e-8f);
    inv.z = 1.f / fmaxf(sqrtf(n2.z), 1e-8f);
    inv.w = 1.f / fmaxf(sqrtf(n2.w), 1e-8f);
#pragma unroll
    for (int l = 0; l < LL; l++) {
        float4 d = make_float4(0.f, 0.f, 0.f, 0.f);
#pragma unroll
        for (int c = 0; c < C; c++) {
            float q = qs[l * C + c];
            d.x += v[c].x * q; d.y += v[c].y * q;
            d.z += v[c].z * q; d.w += v[c].w * q;
        }
        float rq = 1.f / nqs[l];
        d.x *= inv.x * rq; d.y *= inv.y * rq; d.z *= inv.z * rq; d.w *= inv.w * rq;
        *(float4*)(attn + ((size_t)(b * LL + l)) * P + p0) = d;
    }
}

// block ranges: lvl0: [0,32) (16/b), lvl1: [32,40) (4/b), lvl2: [40,42), lvl3: [42,44)
__global__ void attn_all_k(const float* __restrict__ h2p0, const float* __restrict__ h1p0,
                           const float* __restrict__ h2p1, const float* __restrict__ h1p1,
                           const float* __restrict__ h2p2, const float* __restrict__ h1p2,
                           const float* __restrict__ h2p3, const float* __restrict__ h1p3,
                           const int* __restrict__ pts,
                           float* __restrict__ a0, float* __restrict__ a1,
                           float* __restrict__ a2, float* __restrict__ a3) {
    __shared__ float qs[LL * 16];
    __shared__ float nqs[LL];
    int id = blockIdx.x;
    if (id < 32)      attn_level<4, 128, 1>(h2p0, h1p0, pts, a0, id / 16, id % 16, qs, nqs);
    else if (id < 40) attn_level<8, 64, 2>(h2p1, h1p1, pts, a1, (id - 32) / 4, (id - 32) % 4, qs, nqs);
    else if (id < 42) attn_level<16, 32, 3>(h2p2, h1p2, pts, a2, id - 40, 0, qs, nqs);
    else              attn_level<16, 16, 4>(h2p3, h1p3, pts, a3, id - 42, 0, qs, nqs);
}

// ============ fused decoder: concat + upsample2 + concat + conv3x3 + leaky ============
template<int CH2, int CF, int CO, int COG, int HO, bool LEAKY, bool H2MOD>
__global__ void dec_conv_t(const float* __restrict__ h2, const float* __restrict__ attn,
                           const float* __restrict__ feat, const float* __restrict__ w,
                           const float* __restrict__ bias, float* __restrict__ out) {
    constexpr int CIN = CH2 + 1 + CF;
    constexpr int HH = HO / 2;
    constexpr int NG = CO / COG;
    __shared__ float ws[COG * CIN * 9];
    int bly = blockIdx.y;
    int cog = bly % NG;
    int n = bly / NG;
    int co0 = cog * COG;
    for (int i = threadIdx.x; i < COG * CIN * 9; i += blockDim.x)
        ws[i] = w[co0 * CIN * 9 + i];
    __syncthreads();

    int p = blockIdx.x * blockDim.x + threadIdx.x;
    if (p >= HH * HH) return;
    int X = p % HH, Y = p / HH;
    int nh2 = H2MOD ? (n % BB) : n;
    int nf = n % BB;

    float acc[COG][2][2];
#pragma unroll
    for (int g = 0; g < COG; g++) {
        float b = bias[co0 + g];
        acc[g][0][0] = b; acc[g][0][1] = b; acc[g][1][0] = b; acc[g][1][1] = b;
    }

    // ---- half-res channels: CH2 of h2, then 1 of attn ----
    {
        const float* hb = h2 + (size_t)nh2 * CH2 * HH * HH;
#pragma unroll 4
        for (int ci = 0; ci < CH2; ci++) {
            const float* src = hb + ci * HH * HH;
            float v[3][3];
#pragma unroll
            for (int r = 0; r < 3; r++) {
                int hy = Y - 1 + r;
                bool oy = (unsigned)hy < (unsigned)HH;
#pragma unroll
                for (int c = 0; c < 3; c++) {
                    int hx = X - 1 + c;
                    v[r][c] = (oy && (unsigned)hx < (unsigned)HH) ? __ldg(src + hy * HH + hx) : 0.f;
                }
            }
#pragma unroll
            for (int g = 0; g < COG; g++)
#pragma unroll
                for (int dy = 0; dy < 2; dy++)
#pragma unroll
                    for (int dx = 0; dx < 2; dx++)
#pragma unroll
                        for (int ky = 0; ky < 3; ky++)
#pragma unroll
                            for (int kx = 0; kx < 3; kx++)
                                acc[g][dy][dx] += v[((dy + ky - 1) >> 1) + 1][((dx + kx - 1) >> 1) + 1]
                                                  * ws[g * CIN * 9 + ci * 9 + ky * 3 + kx];
        }
        // attn channel (index CH2), batch index n (not modded)
        {
            const float* src = attn + (size_t)n * HH * HH;
            float v[3][3];
#pragma unroll
            for (int r = 0; r < 3; r++) {
                int hy = Y - 1 + r;
                bool oy = (unsigned)hy < (unsigned)HH;
#pragma unroll
                for (int c = 0; c < 3; c++) {
                    int hx = X - 1 + c;
                    v[r][c] = (oy && (unsigned)hx < (unsigned)HH) ? __ldg(src + hy * HH + hx) : 0.f;
                }
            }
#pragma unroll
            for (int g = 0; g < COG; g++)
#pragma unroll
                for (int dy = 0; dy < 2; dy++)
#pragma unroll
                    for (int dx = 0; dx < 2; dx++)
#pragma unroll
                        for (int ky = 0; ky < 3; ky++)
#pragma unroll
                            for (int kx = 0; kx < 3; kx++)
                                acc[g][dy][dx] += v[((dy + ky - 1) >> 1) + 1][((dx + kx - 1) >> 1) + 1]
                                                  * ws[g * CIN * 9 + CH2 * 9 + ky * 3 + kx];
        }
    }

    // ---- full-res feat channels ----
    {
        const float* fb = feat + (size_t)nf * CF * HO * HO;
#pragma unroll 4
        for (int cf = 0; cf < CF; cf++) {
            const float* src = fb + cf * HO * HO;
            float v[4][4];
#pragma unroll
            for (int r = 0; r < 4; r++) {
                int yy = 2 * Y - 1 + r;
                bool oy = (unsigned)yy < (unsigned)HO;
#pragma unroll
                for (int c = 0; c < 4; c++) {
                    int xx = 2 * X - 1 + c;
                    v[r][c] = (oy && (unsigned)xx < (unsigned)HO) ? __ldg(src + yy * HO + xx) : 0.f;
                }
            }
#pragma unroll
            for (int g = 0; g < COG; g++)
#pragma unroll
                for (int dy = 0; dy < 2; dy++)
#pragma unroll
                    for (int dx = 0; dx < 2; dx++)
#pragma unroll
                        for (int ky = 0; ky < 3; ky++)
#pragma unroll
                            for (int kx = 0; kx < 3; kx++)
                                acc[g][dy][dx] += v[dy + ky][dx + kx]
                                                  * ws[g * CIN * 9 + (CH2 + 1 + cf) * 9 + ky * 3 + kx];
        }
    }

#pragma unroll
    for (int g = 0; g < COG; g++)
#pragma unroll
        for (int dy = 0; dy < 2; dy++)
#pragma unroll
            for (int dx = 0; dx < 2; dx++) {
                float r = acc[g][dy][dx];
                if (LEAKY) r = leaky(r);
                out[(((size_t)n * CO + co0 + g) * HO + 2 * Y + dy) * HO + 2 * X + dx] = r;
            }
}

// ---------------- launch ----------------
extern "C" void kernel_launch(void* const* d_in, const int* in_sizes, int n_in,
                              void* d_out, int out_size) {
    const float* x1 = (const float*)d_in[0];
    const float* x2 = (const float*)d_in[1];
    const int* pts = (const int*)d_in[2];
    const float* ew[4] = {(const float*)d_in[3], (const float*)d_in[5],
                          (const float*)d_in[7], (const float*)d_in[9]};
    const float* eb[4] = {(const float*)d_in[4], (const float*)d_in[6],
                          (const float*)d_in[8], (const float*)d_in[10]};
    const float* dw[4] = {(const float*)d_in[11], (const float*)d_in[13],
                          (const float*)d_in[15], (const float*)d_in[17]};
    const float* db[4] = {(const float*)d_in[12], (const float*)d_in[14],
                          (const float*)d_in[16], (const float*)d_in[18]};
    float* out = (float*)d_out;

    float *h1p0, *h1p1, *h1p2, *h1p3;
    float *f0, *f1, *f2, *f3;
    float *h2p0, *h2p1, *h2p2, *h2p3;
    float *a0, *a1, *a2, *a3;
    float *dd0, *dd1, *dd2;
    cudaGetSymbolAddress((void**)&h1p0, g_h1p0);
    cudaGetSymbolAddress((void**)&h1p1, g_h1p1);
    cudaGetSymbolAddress((void**)&h1p2, g_h1p2);
    cudaGetSymbolAddress((void**)&h1p3, g_h1p3);
    cudaGetSymbolAddress((void**)&f0, g_f0);
    cudaGetSymbolAddress((void**)&f1, g_f1);
    cudaGetSymbolAddress((void**)&f2, g_f2);
    cudaGetSymbolAddress((void**)&f3, g_f3);
    cudaGetSymbolAddress((void**)&h2p0, g_h2p0);
    cudaGetSymbolAddress((void**)&h2p1, g_h2p1);
    cudaGetSymbolAddress((void**)&h2p2, g_h2p2);
    cudaGetSymbolAddress((void**)&h2p3, g_h2p3);
    cudaGetSymbolAddress((void**)&a0, g_attn0);
    cudaGetSymbolAddress((void**)&a1, g_attn1);
    cudaGetSymbolAddress((void**)&a2, g_attn2);
    cudaGetSymbolAddress((void**)&a3, g_attn3);
    cudaGetSymbolAddress((void**)&dd0, g_d0);
    cudaGetSymbolAddress((void**)&dd1, g_d1);
    cudaGetSymbolAddress((void**)&dd2, g_d2);

    const int T = 128;

    // ---- encoder chain (both paths per launch), no attn interleaved ----
    enc_conv2_t<3, 4, 4, 256><<<dim3(cdiv(128*128, T), 2*1, 2), T>>>(x2, x1, ew[0], eb[0], f0, h2p0, h1p0);
    enc_conv2_t<4, 8, 4, 128><<<dim3(cdiv(64*64, T), 2*2, 2), T>>>(h2p0, h1p0, ew[1], eb[1], f1, h2p1, h1p1);
    enc_conv2_t<8, 16, 4, 64><<<dim3(cdiv(32*32, T), 2*4, 2), T>>>(h2p1, h1p1, ew[2], eb[2], f2, h2p2, h1p2);
    enc_conv2_t<16, 16, 4, 32><<<dim3(cdiv(16*16, T), 2*4, 2), T>>>(h2p2, h1p2, ew[3], eb[3], f3, h2p3, h1p3);

    // ---- all attention levels in one kernel ----
    attn_all_k<<<44, 256>>>(h2p0, h1p0, h2p1, h1p1, h2p2, h1p2, h2p3, h1p3,
                            pts, a0, a1, a2, a3);

    // ---- decoder ----
    // dec0: h2p3 (16ch @16, tiled->n%B) + attn3 + f3(16ch @32) -> 16ch @32, COG=8
    dec_conv_t<16, 16, 16, 8, 32, true, true><<<dim3(cdiv(16*16, T), 64*2), T>>>(h2p3, a3, f3, dw[0], db[0], dd0);
    // dec1: dd0 (16ch @32) + attn2 + f2(16ch @64) -> 8ch @64, COG=8
    dec_conv_t<16, 16, 8, 8, 64, true, false><<<dim3(cdiv(32*32, T), 64*1), T>>>(dd0, a2, f2, dw[1], db[1], dd1);
    // dec2: dd1 (8ch @64) + attn1 + f1(8ch @128) -> 4ch @128
    dec_conv_t<8, 8, 4, 4, 128, true, false><<<dim3(cdiv(64*64, T), 64*1), T>>>(dd1, a1, f1, dw[2], db[2], dd2);
    // dec3: dd2 (4ch @128) + attn0 + f0(4ch @256) -> 1ch @256, NO leaky
    dec_conv_t<4, 4, 1, 1, 256, false, false><<<dim3(cdiv(128*128, T), 64*1), T>>>(dd2, a0, f0, dw[3], db[3], out);
}

// round 6
// speedup vs baseline: 6.9057x; 1.0980x over previous
#include <cuda_runtime.h>
#include <math.h>

#define BB 2
#define LL 32
#define NSLOPE 0.01f

// ---------------- scratch (static __device__, no allocs) ----------------
__device__ float g_h1p0[2*4*128*128];
__device__ float g_h1p1[2*8*64*64];
__device__ float g_h1p2[2*16*32*32];
__device__ float g_h1p3[2*16*16*16];

__device__ float g_f0[2*4*256*256];
__device__ float g_f1[2*8*128*128];
__device__ float g_f2[2*16*64*64];
__device__ float g_f3[2*16*32*32];

__device__ float g_h2p0[2*4*128*128];
__device__ float g_h2p1[2*8*64*64];
__device__ float g_h2p2[2*16*32*32];
__device__ float g_h2p3[2*16*16*16];

__device__ float g_attn0[64*128*128];
__device__ float g_attn1[64*64*64];
__device__ float g_attn2[64*32*32];
__device__ float g_attn3[64*16*16];

__device__ float g_d0[64*16*32*32];
__device__ float g_d1[64*8*64*64];
__device__ float g_d2[64*4*128*128];

static inline int cdiv(int a, int b) { return (a + b - 1) / b; }

__device__ __forceinline__ float leaky(float v) { return v >= 0.f ? v : NSLOPE * v; }

// Build per-parity 2x2 effective kernel from a 3x3 kernel (upsample-nearest folding).
// ey/ex = output-pixel parity. e[a*2+b] = sum of w taps landing on half-res px (a,b).
__device__ __forceinline__ void build_eff(const float* wk, int ey, int ex, float* e) {
    float rs[2][3];
    if (ey == 0) {
        rs[0][0] = wk[0]; rs[0][1] = wk[1]; rs[0][2] = wk[2];
        rs[1][0] = wk[3] + wk[6]; rs[1][1] = wk[4] + wk[7]; rs[1][2] = wk[5] + wk[8];
    } else {
        rs[0][0] = wk[0] + wk[3]; rs[0][1] = wk[1] + wk[4]; rs[0][2] = wk[2] + wk[5];
        rs[1][0] = wk[6]; rs[1][1] = wk[7]; rs[1][2] = wk[8];
    }
#pragma unroll
    for (int a = 0; a < 2; a++) {
        if (ex == 0) { e[a * 2 + 0] = rs[a][0]; e[a * 2 + 1] = rs[a][1] + rs[a][2]; }
        else         { e[a * 2 + 0] = rs[a][0] + rs[a][1]; e[a * 2 + 1] = rs[a][2]; }
    }
}

// ============ encoder: conv5x5+leaky[+feats]+maxpool2, ci-split S, both paths (z) ============
template<int CI, int CO, int COG, int H, int S, int PPB>
__global__ void enc_conv3_t(const float* __restrict__ in2, const float* __restrict__ in1,
                            const float* __restrict__ w, const float* __restrict__ bias,
                            float* __restrict__ f, float* __restrict__ pooled2,
                            float* __restrict__ pooled1) {
    constexpr int HP = H / 2;
    constexpr int NG = CO / COG;
    constexpr int CIG = CI / S;
    static_assert(CI % S == 0, "");
    static_assert((HP * HP) % PPB == 0, "");
    __shared__ float ws[COG * CI * 25];
    __shared__ float red[(S > 1) ? (S - 1) * PPB * COG * 4 : 1];

    int bly = blockIdx.y;
    int cog = bly % NG;
    int n = bly / NG;
    int co0 = cog * COG;
    bool path2 = (blockIdx.z == 0);
    const float* in = path2 ? in2 : in1;
    float* pooled = path2 ? pooled2 : pooled1;

    int tx = threadIdx.x, ty = threadIdx.y;
    int tid = ty * PPB + tx;
    for (int i = tid; i < COG * CI * 25; i += PPB * S)
        ws[i] = w[co0 * CI * 25 + i];
    __syncthreads();

    int p = blockIdx.x * PPB + tx;
    int px = p % HP, py = p / HP;

    float acc[COG][2][2] = {};

    const float* ib = in + (size_t)n * CI * H * H;
#pragma unroll
    for (int i = 0; i < CIG; i++) {
        int ci = ty * CIG + i;
        const float* src = ib + ci * H * H;
        float v[6][6];
#pragma unroll
        for (int r = 0; r < 6; r++) {
            int yy = 2 * py - 2 + r;
            bool oy = (unsigned)yy < (unsigned)H;
#pragma unroll
            for (int c = 0; c < 6; c++) {
                int xx = 2 * px - 2 + c;
                v[r][c] = (oy && (unsigned)xx < (unsigned)H) ? __ldg(src + yy * H + xx) : 0.f;
            }
        }
#pragma unroll
        for (int g = 0; g < COG; g++)
#pragma unroll
            for (int dy = 0; dy < 2; dy++)
#pragma unroll
                for (int dx = 0; dx < 2; dx++)
#pragma unroll
                    for (int ky = 0; ky < 5; ky++)
#pragma unroll
                        for (int kx = 0; kx < 5; kx++)
                            acc[g][dy][dx] += v[dy + ky][dx + kx] * ws[(g * CI + ci) * 25 + ky * 5 + kx];
    }

    if constexpr (S > 1) {
        if (ty > 0) {
            float* r = &red[((ty - 1) * PPB + tx) * (COG * 4)];
#pragma unroll
            for (int g = 0; g < COG; g++)
#pragma unroll
                for (int dy = 0; dy < 2; dy++)
#pragma unroll
                    for (int dx = 0; dx < 2; dx++)
                        r[g * 4 + dy * 2 + dx] = acc[g][dy][dx];
        }
        __syncthreads();
        if (ty > 0) return;
#pragma unroll
        for (int s = 0; s < S - 1; s++) {
            const float* r = &red[(s * PPB + tx) * (COG * 4)];
#pragma unroll
            for (int g = 0; g < COG; g++)
#pragma unroll
                for (int dy = 0; dy < 2; dy++)
#pragma unroll
                    for (int dx = 0; dx < 2; dx++)
                        acc[g][dy][dx] += r[g * 4 + dy * 2 + dx];
        }
    }

#pragma unroll
    for (int g = 0; g < COG; g++) {
        float b = bias[co0 + g];
        float a00 = leaky(acc[g][0][0] + b);
        float a01 = leaky(acc[g][0][1] + b);
        float a10 = leaky(acc[g][1][0] + b);
        float a11 = leaky(acc[g][1][1] + b);
        int coidx = n * CO + co0 + g;
        if (path2) {
            float* fp = f + (size_t)coidx * H * H;
            fp[(2 * py) * H + 2 * px] = a00;
            fp[(2 * py) * H + 2 * px + 1] = a01;
            fp[(2 * py + 1) * H + 2 * px] = a10;
            fp[(2 * py + 1) * H + 2 * px + 1] = a11;
        }
        pooled[((size_t)coidx * HP + py) * HP + px] = fmaxf(fmaxf(a00, a01), fmaxf(a10, a11));
    }
}

// ============ attention, all 4 levels in one kernel ============
template<int C, int HS, int SHIFT>
__device__ __forceinline__ void attn_level(const float* __restrict__ h2p,
                                           const float* __restrict__ h1p,
                                           const int* __restrict__ pts,
                                           float* __restrict__ attn,
                                           int b, int blk, float* qs, float* nqs) {
    constexpr int P = HS * HS;
    int tid = threadIdx.x;
    for (int i = tid; i < LL * C; i += blockDim.x) {
        int l = i / C, c = i % C;
        int qr = pts[(b * LL + l) * 2 + 0] >> SHIFT;
        int qc = pts[(b * LL + l) * 2 + 1] >> SHIFT;
        qs[l * C + c] = h1p[((size_t)(b * C + c)) * P + qr * HS + qc];
    }
    __syncthreads();
    if (tid < LL) {
        float s = 0.f;
#pragma unroll
        for (int c = 0; c < C; c++) s += qs[tid * C + c] * qs[tid * C + c];
        nqs[tid] = fmaxf(sqrtf(s), 1e-8f);
    }
    __syncthreads();

    int p0 = (blk * (int)blockDim.x + tid) * 4;
    if (p0 >= P) return;
    float4 v[C];
    float4 n2 = make_float4(0.f, 0.f, 0.f, 0.f);
#pragma unroll
    for (int c = 0; c < C; c++) {
        v[c] = *(const float4*)(h2p + ((size_t)(b * C + c)) * P + p0);
        n2.x += v[c].x * v[c].x; n2.y += v[c].y * v[c].y;
        n2.z += v[c].z * v[c].z; n2.w += v[c].w * v[c].w;
    }
    float4 inv;
    inv.x = 1.f / fmaxf(sqrtf(n2.x), 1e-8f);
    inv.y = 1.f / fmaxf(sqrtf(n2.y), 1e-8f);
    inv.z = 1.f / fmaxf(sqrtf(n2.z), 1e-8f);
    inv.w = 1.f / fmaxf(sqrtf(n2.w), 1e-8f);
#pragma unroll
    for (int l = 0; l < LL; l++) {
        float4 d = make_float4(0.f, 0.f, 0.f, 0.f);
#pragma unroll
        for (int c = 0; c < C; c++) {
            float q = qs[l * C + c];
            d.x += v[c].x * q; d.y += v[c].y * q;
            d.z += v[c].z * q; d.w += v[c].w * q;
        }
        float rq = 1.f / nqs[l];
        d.x *= inv.x * rq; d.y *= inv.y * rq; d.z *= inv.z * rq; d.w *= inv.w * rq;
        *(float4*)(attn + ((size_t)(b * LL + l)) * P + p0) = d;
    }
}

__global__ void attn_all_k(const float* __restrict__ h2p0, const float* __restrict__ h1p0,
                           const float* __restrict__ h2p1, const float* __restrict__ h1p1,
                           const float* __restrict__ h2p2, const float* __restrict__ h1p2,
                           const float* __restrict__ h2p3, const float* __restrict__ h1p3,
                           const int* __restrict__ pts,
                           float* __restrict__ a0, float* __restrict__ a1,
                           float* __restrict__ a2, float* __restrict__ a3) {
    __shared__ float qs[LL * 16];
    __shared__ float nqs[LL];
    int id = blockIdx.x;
    if (id < 32)      attn_level<4, 128, 1>(h2p0, h1p0, pts, a0, id / 16, id % 16, qs, nqs);
    else if (id < 40) attn_level<8, 64, 2>(h2p1, h1p1, pts, a1, (id - 32) / 4, (id - 32) % 4, qs, nqs);
    else if (id < 42) attn_level<16, 32, 3>(h2p2, h1p2, pts, a2, id - 40, 0, qs, nqs);
    else              attn_level<16, 16, 4>(h2p3, h1p3, pts, a3, id - 42, 0, qs, nqs);
}

// ============ fused decoder: eff-kernel half-res + direct feat, split S (half/feat) ============
template<int CH2, int CF, int CO, int COG, int HO, bool LEAKY, bool H2MOD, int S, int PPB>
__global__ void dec_conv3_t(const float* __restrict__ h2, const float* __restrict__ attn,
                            const float* __restrict__ feat, const float* __restrict__ w,
                            const float* __restrict__ bias, float* __restrict__ out) {
    constexpr int CIN = CH2 + 1 + CF;
    constexpr int CHALF = CH2 + 1;
    constexpr int HH = HO / 2;
    constexpr int NG = CO / COG;
    static_assert((HH * HH) % PPB == 0, "");
    __shared__ float ws[COG * CIN * 9];
    __shared__ float weff[COG * CHALF * 16];
    __shared__ float red[(S > 1) ? PPB * COG * 4 : 1];

    int bly = blockIdx.y;
    int cog = bly % NG;
    int n = bly / NG;
    int co0 = cog * COG;
    int tx = threadIdx.x, ty = threadIdx.y;
    int tid = ty * PPB + tx;
    for (int i = tid; i < COG * CIN * 9; i += PPB * S)
        ws[i] = w[co0 * CIN * 9 + i];
    __syncthreads();
    for (int i = tid; i < COG * CHALF * 4; i += PPB * S) {
        int par = i & 3;
        int gc = i >> 2;
        int g = gc / CHALF, ch = gc % CHALF;
        float e[4];
        build_eff(&ws[(g * CIN + ch) * 9], par >> 1, par & 1, e);
        float* o = &weff[gc * 16 + par * 4];
        o[0] = e[0]; o[1] = e[1]; o[2] = e[2]; o[3] = e[3];
    }
    __syncthreads();

    int p = blockIdx.x * PPB + tx;
    int X = p % HH, Y = p / HH;
    int nh2 = H2MOD ? (n % BB) : n;
    int nf = n % BB;

    float acc[COG][2][2] = {};

    // ---- half-res channels (h2 + attn) via per-parity 2x2 effective kernels ----
    if (S == 1 || ty == 0) {
        const float* hb = h2 + (size_t)nh2 * CH2 * HH * HH;
        const float* ab = attn + (size_t)n * HH * HH;
#pragma unroll 4
        for (int ch = 0; ch < CHALF; ch++) {
            const float* src = (ch < CH2) ? (hb + ch * HH * HH) : ab;
            float v[3][3];
#pragma unroll
            for (int r = 0; r < 3; r++) {
                int hy = Y - 1 + r;
                bool oy = (unsigned)hy < (unsigned)HH;
#pragma unroll
                for (int c = 0; c < 3; c++) {
                    int hx = X - 1 + c;
                    v[r][c] = (oy && (unsigned)hx < (unsigned)HH) ? __ldg(src + hy * HH + hx) : 0.f;
                }
            }
#pragma unroll
            for (int g = 0; g < COG; g++) {
                const float* wf = &weff[(g * CHALF + ch) * 16];
#pragma unroll
                for (int dy = 0; dy < 2; dy++)
#pragma unroll
                    for (int dx = 0; dx < 2; dx++)
#pragma unroll
                        for (int a = 0; a < 2; a++)
#pragma unroll
                            for (int b = 0; b < 2; b++)
                                acc[g][dy][dx] += v[((dy + 1) >> 1) + a][((dx + 1) >> 1) + b]
                                                  * wf[(dy * 2 + dx) * 4 + a * 2 + b];
            }
        }
    }

    // ---- full-res feat channels ----
    if (S == 1 || ty == 1) {
        const float* fb = feat + (size_t)nf * CF * HO * HO;
#pragma unroll 4
        for (int cf = 0; cf < CF; cf++) {
            const float* src = fb + cf * HO * HO;
            float v[4][4];
#pragma unroll
            for (int r = 0; r < 4; r++) {
                int yy = 2 * Y - 1 + r;
                bool oy = (unsigned)yy < (unsigned)HO;
#pragma unroll
                for (int c = 0; c < 4; c++) {
                    int xx = 2 * X - 1 + c;
                    v[r][c] = (oy && (unsigned)xx < (unsigned)HO) ? __ldg(src + yy * HO + xx) : 0.f;
                }
            }
#pragma unroll
            for (int g = 0; g < COG; g++)
#pragma unroll
                for (int dy = 0; dy < 2; dy++)
#pragma unroll
                    for (int dx = 0; dx < 2; dx++)
#pragma unroll
                        for (int ky = 0; ky < 3; ky++)
#pragma unroll
                            for (int kx = 0; kx < 3; kx++)
                                acc[g][dy][dx] += v[dy + ky][dx + kx]
                                                  * ws[(g * CIN + CH2 + 1 + cf) * 9 + ky * 3 + kx];
        }
    }

    if constexpr (S > 1) {
        if (ty == 1) {
            float* r = &red[tx * (COG * 4)];
#pragma unroll
            for (int g = 0; g < COG; g++)
#pragma unroll
                for (int dy = 0; dy < 2; dy++)
#pragma unroll
                    for (int dx = 0; dx < 2; dx++)
                        r[g * 4 + dy * 2 + dx] = acc[g][dy][dx];
        }
        __syncthreads();
        if (ty == 1) return;
        const float* r = &red[tx * (COG * 4)];
#pragma unroll
        for (int g = 0; g < COG; g++)
#pragma unroll
            for (int dy = 0; dy < 2; dy++)
#pragma unroll
                for (int dx = 0; dx < 2; dx++)
                    acc[g][dy][dx] += r[g * 4 + dy * 2 + dx];
    }

#pragma unroll
    for (int g = 0; g < COG; g++) {
        float b = bias[co0 + g];
#pragma unroll
        for (int dy = 0; dy < 2; dy++)
#pragma unroll
            for (int dx = 0; dx < 2; dx++) {
                float r = acc[g][dy][dx] + b;
                if (LEAKY) r = leaky(r);
                out[(((size_t)n * CO + co0 + g) * HO + 2 * Y + dy) * HO + 2 * X + dx] = r;
            }
    }
}

// ============ final decoder layer: CO=1, 4x4 output patch, eff-kernel half-res ============
template<int CH2, int CF, int HO, bool LEAKY>
__global__ void dec_conv_p4_t(const float* __restrict__ h2, const float* __restrict__ attn,
                              const float* __restrict__ feat, const float* __restrict__ w,
                              const float* __restrict__ bias, float* __restrict__ out) {
    constexpr int CIN = CH2 + 1 + CF;
    constexpr int CHALF = CH2 + 1;
    constexpr int HH = HO / 2;
    constexpr int QH = HO / 4;
    __shared__ float ws[CIN * 9];
    __shared__ float weff[CHALF * 16];
    int n = blockIdx.y;
    int tid = threadIdx.x;
    for (int i = tid; i < CIN * 9; i += blockDim.x) ws[i] = w[i];
    __syncthreads();
    for (int i = tid; i < CHALF * 4; i += blockDim.x) {
        int par = i & 3, ch = i >> 2;
        float e[4];
        build_eff(&ws[ch * 9], par >> 1, par & 1, e);
        float* o = &weff[ch * 16 + par * 4];
        o[0] = e[0]; o[1] = e[1]; o[2] = e[2]; o[3] = e[3];
    }
    __syncthreads();

    int p = blockIdx.x * blockDim.x + tid;
    int X = p % QH, Y = p / QH;   // out patch origin (4Y, 4X); half-res origin (2Y, 2X)
    int nf = n % BB;

    float acc[4][4] = {};

    // half-res channels: 4x4 halo at rows 2Y-1..2Y+2
    {
        const float* hb = h2 + (size_t)n * CH2 * HH * HH;
        const float* ab = attn + (size_t)n * HH * HH;
#pragma unroll
        for (int ch = 0; ch < CHALF; ch++) {
            const float* src = (ch < CH2) ? (hb + ch * HH * HH) : ab;
            float v[4][4];
#pragma unroll
            for (int r = 0; r < 4; r++) {
                int hy = 2 * Y - 1 + r;
                bool oy = (unsigned)hy < (unsigned)HH;
#pragma unroll
                for (int c = 0; c < 4; c++) {
                    int hx = 2 * X - 1 + c;
                    v[r][c] = (oy && (unsigned)hx < (unsigned)HH) ? __ldg(src + hy * HH + hx) : 0.f;
                }
            }
            const float* wf = &weff[ch * 16];
#pragma unroll
            for (int dy = 0; dy < 4; dy++)
#pragma unroll
                for (int dx = 0; dx < 4; dx++)
#pragma unroll
                    for (int a = 0; a < 2; a++)
#pragma unroll
                        for (int b = 0; b < 2; b++)
                            acc[dy][dx] += v[((dy + 1) >> 1) + a][((dx + 1) >> 1) + b]
                                           * wf[((dy & 1) * 2 + (dx & 1)) * 4 + a * 2 + b];
        }
    }

    // full-res feat channels: 6x6 halo at rows 4Y-1..4Y+4
    {
        const float* fb = feat + (size_t)nf * CF * HO * HO;
#pragma unroll
        for (int cf = 0; cf < CF; cf++) {
            const float* src = fb + cf * HO * HO;
            float v[6][6];
#pragma unroll
            for (int r = 0; r < 6; r++) {
                int yy = 4 * Y - 1 + r;
                bool oy = (unsigned)yy < (unsigned)HO;
#pragma unroll
                for (int c = 0; c < 6; c++) {
                    int xx = 4 * X - 1 + c;
                    v[r][c] = (oy && (unsigned)xx < (unsigned)HO) ? __ldg(src + yy * HO + xx) : 0.f;
                }
            }
            const float* wk = &ws[(CHALF + cf) * 9];
#pragma unroll
            for (int dy = 0; dy < 4; dy++)
#pragma unroll
                for (int dx = 0; dx < 4; dx++)
#pragma unroll
                    for (int ky = 0; ky < 3; ky++)
#pragma unroll
                        for (int kx = 0; kx < 3; kx++)
                            acc[dy][dx] += v[dy + ky][dx + kx] * wk[ky * 3 + kx];
        }
    }

    float b = bias[0];
#pragma unroll
    for (int dy = 0; dy < 4; dy++)
#pragma unroll
        for (int dx = 0; dx < 4; dx++) {
            float r = acc[dy][dx] + b;
            if (LEAKY) r = leaky(r);
            out[((size_t)n * HO + 4 * Y + dy) * HO + 4 * X + dx] = r;
        }
}

// ---------------- launch ----------------
extern "C" void kernel_launch(void* const* d_in, const int* in_sizes, int n_in,
                              void* d_out, int out_size) {
    const float* x1 = (const float*)d_in[0];
    const float* x2 = (const float*)d_in[1];
    const int* pts = (const int*)d_in[2];
    const float* ew[4] = {(const float*)d_in[3], (const float*)d_in[5],
                          (const float*)d_in[7], (const float*)d_in[9]};
    const float* eb[4] = {(const float*)d_in[4], (const float*)d_in[6],
                          (const float*)d_in[8], (const float*)d_in[10]};
    const float* dw[4] = {(const float*)d_in[11], (const float*)d_in[13],
                          (const float*)d_in[15], (const float*)d_in[17]};
    const float* db[4] = {(const float*)d_in[12], (const float*)d_in[14],
                          (const float*)d_in[16], (const float*)d_in[18]};
    float* out = (float*)d_out;

    float *h1p0, *h1p1, *h1p2, *h1p3;
    float *f0, *f1, *f2, *f3;
    float *h2p0, *h2p1, *h2p2, *h2p3;
    float *a0, *a1, *a2, *a3;
    float *dd0, *dd1, *dd2;
    cudaGetSymbolAddress((void**)&h1p0, g_h1p0);
    cudaGetSymbolAddress((void**)&h1p1, g_h1p1);
    cudaGetSymbolAddress((void**)&h1p2, g_h1p2);
    cudaGetSymbolAddress((void**)&h1p3, g_h1p3);
    cudaGetSymbolAddress((void**)&f0, g_f0);
    cudaGetSymbolAddress((void**)&f1, g_f1);
    cudaGetSymbolAddress((void**)&f2, g_f2);
    cudaGetSymbolAddress((void**)&f3, g_f3);
    cudaGetSymbolAddress((void**)&h2p0, g_h2p0);
    cudaGetSymbolAddress((void**)&h2p1, g_h2p1);
    cudaGetSymbolAddress((void**)&h2p2, g_h2p2);
    cudaGetSymbolAddress((void**)&h2p3, g_h2p3);
    cudaGetSymbolAddress((void**)&a0, g_attn0);
    cudaGetSymbolAddress((void**)&a1, g_attn1);
    cudaGetSymbolAddress((void**)&a2, g_attn2);
    cudaGetSymbolAddress((void**)&a3, g_attn3);
    cudaGetSymbolAddress((void**)&dd0, g_d0);
    cudaGetSymbolAddress((void**)&dd1, g_d1);
    cudaGetSymbolAddress((void**)&dd2, g_d2);

    // ---- encoder chain (both paths per launch), ci-split on deep levels ----
    enc_conv3_t<3, 4, 4, 256, 1, 128><<<dim3(128, 2, 2), dim3(128, 1)>>>(x2, x1, ew[0], eb[0], f0, h2p0, h1p0);
    enc_conv3_t<4, 8, 4, 128, 2, 64><<<dim3(64, 4, 2), dim3(64, 2)>>>(h2p0, h1p0, ew[1], eb[1], f1, h2p1, h1p1);
    enc_conv3_t<8, 16, 4, 64, 2, 64><<<dim3(16, 8, 2), dim3(64, 2)>>>(h2p1, h1p1, ew[2], eb[2], f2, h2p2, h1p2);
    enc_conv3_t<16, 16, 4, 32, 4, 64><<<dim3(4, 8, 2), dim3(64, 4)>>>(h2p2, h1p2, ew[3], eb[3], f3, h2p3, h1p3);

    // ---- all attention levels in one kernel ----
    attn_all_k<<<44, 256>>>(h2p0, h1p0, h2p1, h1p1, h2p2, h1p2, h2p3, h1p3,
                            pts, a0, a1, a2, a3);

    // ---- decoder ----
    dec_conv3_t<16, 16, 16, 8, 32, true, true, 2, 64><<<dim3(4, 128), dim3(64, 2)>>>(h2p3, a3, f3, dw[0], db[0], dd0);
    dec_conv3_t<16, 16, 8, 8, 64, true, false, 2, 64><<<dim3(16, 64), dim3(64, 2)>>>(dd0, a2, f2, dw[1], db[1], dd1);
    dec_conv3_t<8, 8, 4, 4, 128, true, false, 2, 64><<<dim3(64, 64), dim3(64, 2)>>>(dd1, a1, f1, dw[2], db[2], dd2);
    dec_conv_p4_t<4, 4, 256, false><<<dim3(32, 64), 128>>>(dd2, a0, f0, dw[3], db[3], out);
}